// round 2
// baseline (speedup 1.0000x reference)
#include <cuda_runtime.h>
#include <cstddef>

// Problem constants (fixed shapes per reference)
#define T_STEPS 336
#define BATCH   1024
#define IN      16
#define H       64
#define G       256        // 4*H
#define NB      8          // batch elements per CTA
#define NTHREADS 128
#define NCTAS   (BATCH/NB) // 128
#define RS      260        // padded row stride (floats) for transposed weights

// ---- shared memory layout (float offsets) ----
#define OFF_WIH0 0
#define OFF_WHH0 (OFF_WIH0 + IN*RS)          // 16 rows
#define OFF_WIH1 (OFF_WHH0 + H*RS)           // 64 rows
#define OFF_WHH1 (OFF_WIH1 + H*RS)           // 64 rows
#define OFF_B0   (OFF_WHH1 + H*RS)           // 256
#define OFF_B1   (OFF_B0 + G)                // 256
#define OFF_WFC  (OFF_B1 + G)                // 64
#define OFF_X    (OFF_WFC + H)               // 16*NB = 128
#define OFF_H0   (OFF_X + IN*NB)             // 2*NB*H = 1024
#define OFF_H1   (OFF_H0 + 2*NB*H)           // 1024
#define SMEM_FLOATS (OFF_H1 + 2*NB*H)
#define SMEM_BYTES (SMEM_FLOATS * 4)         // 227,328 B (< 232,448 cap)

__device__ __forceinline__ float sigf(float x) {
    return 1.0f / (1.0f + __expf(-x));
}
__device__ __forceinline__ float tanh_ex(float x) {
    // 1 - 2/(e^{2x}+1): saturates correctly at +/-1 for large |x|
    return 1.0f - 2.0f / (__expf(2.0f * x) + 1.0f);
}
__device__ __forceinline__ void fma4(float4& a, const float4 w, const float s) {
    a.x = fmaf(w.x, s, a.x);
    a.y = fmaf(w.y, s, a.y);
    a.z = fmaf(w.z, s, a.z);
    a.w = fmaf(w.w, s, a.w);
}
__device__ __forceinline__ float4 ld4(const float* p) {
    return *reinterpret_cast<const float4*>(p);
}

__global__ void __launch_bounds__(NTHREADS, 1)
lstm2_kernel(const float* __restrict__ x,
             const float* __restrict__ Wih0, const float* __restrict__ Whh0,
             const float* __restrict__ bih0, const float* __restrict__ bhh0,
             const float* __restrict__ Wih1, const float* __restrict__ Whh1,
             const float* __restrict__ bih1, const float* __restrict__ bhh1,
             const float* __restrict__ Wfc,  const float* __restrict__ bfc,
             float* __restrict__ out)
{
    extern __shared__ float sh[];
    const int tid = threadIdx.x;

    // ---- Stage weights (transposed: sh[k*RS + g] = W[g][k]) ----
    for (int idx = tid; idx < G * IN; idx += NTHREADS) {
        int g = idx >> 4, k = idx & 15;
        sh[OFF_WIH0 + k * RS + g] = Wih0[idx];
    }
    for (int idx = tid; idx < G * H; idx += NTHREADS) {
        int g = idx >> 6, k = idx & 63;
        sh[OFF_WHH0 + k * RS + g] = Whh0[idx];
    }
    for (int idx = tid; idx < G * H; idx += NTHREADS) {
        int g = idx >> 6, k = idx & 63;
        sh[OFF_WIH1 + k * RS + g] = Wih1[idx];
    }
    for (int idx = tid; idx < G * H; idx += NTHREADS) {
        int g = idx >> 6, k = idx & 63;
        sh[OFF_WHH1 + k * RS + g] = Whh1[idx];
    }
    for (int idx = tid; idx < G; idx += NTHREADS) {
        sh[OFF_B0 + idx] = bih0[idx] + bhh0[idx];
        sh[OFF_B1 + idx] = bih1[idx] + bhh1[idx];
    }
    if (tid < H) sh[OFF_WFC + tid] = Wfc[tid];
    for (int idx = tid; idx < 2 * NB * H; idx += NTHREADS) {
        sh[OFF_H0 + idx] = 0.0f;
        sh[OFF_H1 + idx] = 0.0f;
    }

    // ---- thread mapping: half-warp = one batch element; lane owns 4 j's ----
    const int lane = tid & 31;
    const int e    = ((tid >> 5) << 1) + (lane >> 4);  // 0..7 element in CTA
    const int hl   = lane & 15;
    const int j0   = hl << 2;                          // hidden base index

    // x prefetch mapping: thread -> (element, input idx)
    const int xe = tid >> 4, xi = tid & 15;
    const float* xptr = x + (size_t)(blockIdx.x * NB + xe) * T_STEPS * IN + xi;
    float xreg = xptr[0];

    __syncthreads();

    // Biases into registers (loaded once)
    const float4 Bi0 = ld4(&sh[OFF_B0 +   0 + j0]);
    const float4 Bf0 = ld4(&sh[OFF_B0 +  64 + j0]);
    const float4 Bg0 = ld4(&sh[OFF_B0 + 128 + j0]);
    const float4 Bo0 = ld4(&sh[OFF_B0 + 192 + j0]);
    const float4 Bi1 = ld4(&sh[OFF_B1 +   0 + j0]);
    const float4 Bf1 = ld4(&sh[OFF_B1 +  64 + j0]);
    const float4 Bg1 = ld4(&sh[OFF_B1 + 128 + j0]);
    const float4 Bo1 = ld4(&sh[OFF_B1 + 192 + j0]);
    const float4 Wf4 = ld4(&sh[OFF_WFC + j0]);

    float4 C0  = make_float4(0.f, 0.f, 0.f, 0.f);
    float4 C1  = make_float4(0.f, 0.f, 0.f, 0.f);
    float4 H1r = make_float4(0.f, 0.f, 0.f, 0.f);

    int p = 0;
    for (int t = 0; t < T_STEPS; ++t) {
        // publish x(t); barrier also orders previous step's h1 writes
        sh[OFF_X + xi * NB + xe] = xreg;
        __syncthreads();

        // ================= Layer 0 =================
        float4 Ai = Bi0, Af = Bf0, Ag = Bg0, Ao = Bo0;

        #pragma unroll
        for (int k = 0; k < IN; ++k) {
            const float xv = sh[OFF_X + k * NB + e];
            const float* wr = &sh[OFF_WIH0 + k * RS + j0];
            fma4(Ai, ld4(wr      ), xv);
            fma4(Af, ld4(wr +  64), xv);
            fma4(Ag, ld4(wr + 128), xv);
            fma4(Ao, ld4(wr + 192), xv);
        }
        {
            const float* hb = &sh[OFF_H0 + p * (NB * H) + e * H];
            #pragma unroll 8
            for (int k = 0; k < H; ++k) {
                const float hv = hb[k];
                const float* wr = &sh[OFF_WHH0 + k * RS + j0];
                fma4(Ai, ld4(wr      ), hv);
                fma4(Af, ld4(wr +  64), hv);
                fma4(Ag, ld4(wr + 128), hv);
                fma4(Ao, ld4(wr + 192), hv);
            }
        }
        float4 Hn;
        {
            float i_, f_, g_, o_, c_;
            i_ = sigf(Ai.x); f_ = sigf(Af.x); g_ = tanh_ex(Ag.x); o_ = sigf(Ao.x);
            c_ = fmaf(f_, C0.x, i_ * g_); C0.x = c_; Hn.x = o_ * tanh_ex(c_);
            i_ = sigf(Ai.y); f_ = sigf(Af.y); g_ = tanh_ex(Ag.y); o_ = sigf(Ao.y);
            c_ = fmaf(f_, C0.y, i_ * g_); C0.y = c_; Hn.y = o_ * tanh_ex(c_);
            i_ = sigf(Ai.z); f_ = sigf(Af.z); g_ = tanh_ex(Ag.z); o_ = sigf(Ao.z);
            c_ = fmaf(f_, C0.z, i_ * g_); C0.z = c_; Hn.z = o_ * tanh_ex(c_);
            i_ = sigf(Ai.w); f_ = sigf(Af.w); g_ = tanh_ex(Ag.w); o_ = sigf(Ao.w);
            c_ = fmaf(f_, C0.w, i_ * g_); C0.w = c_; Hn.w = o_ * tanh_ex(c_);
        }
        *reinterpret_cast<float4*>(&sh[OFF_H0 + (1 - p) * (NB * H) + e * H + j0]) = Hn;

        // prefetch next x while smem settles
        if (t + 1 < T_STEPS) xreg = xptr[(size_t)(t + 1) * IN];
        __syncthreads();

        // ================= Layer 1 =================
        Ai = Bi1; Af = Bf1; Ag = Bg1; Ao = Bo1;
        {
            const float* hin = &sh[OFF_H0 + (1 - p) * (NB * H) + e * H];
            #pragma unroll 8
            for (int k = 0; k < H; ++k) {
                const float hv = hin[k];
                const float* wr = &sh[OFF_WIH1 + k * RS + j0];
                fma4(Ai, ld4(wr      ), hv);
                fma4(Af, ld4(wr +  64), hv);
                fma4(Ag, ld4(wr + 128), hv);
                fma4(Ao, ld4(wr + 192), hv);
            }
            const float* hb1 = &sh[OFF_H1 + p * (NB * H) + e * H];
            #pragma unroll 8
            for (int k = 0; k < H; ++k) {
                const float hv = hb1[k];
                const float* wr = &sh[OFF_WHH1 + k * RS + j0];
                fma4(Ai, ld4(wr      ), hv);
                fma4(Af, ld4(wr +  64), hv);
                fma4(Ag, ld4(wr + 128), hv);
                fma4(Ao, ld4(wr + 192), hv);
            }
        }
        {
            float i_, f_, g_, o_, c_;
            i_ = sigf(Ai.x); f_ = sigf(Af.x); g_ = tanh_ex(Ag.x); o_ = sigf(Ao.x);
            c_ = fmaf(f_, C1.x, i_ * g_); C1.x = c_; H1r.x = o_ * tanh_ex(c_);
            i_ = sigf(Ai.y); f_ = sigf(Af.y); g_ = tanh_ex(Ag.y); o_ = sigf(Ao.y);
            c_ = fmaf(f_, C1.y, i_ * g_); C1.y = c_; H1r.y = o_ * tanh_ex(c_);
            i_ = sigf(Ai.z); f_ = sigf(Af.z); g_ = tanh_ex(Ag.z); o_ = sigf(Ao.z);
            c_ = fmaf(f_, C1.z, i_ * g_); C1.z = c_; H1r.z = o_ * tanh_ex(c_);
            i_ = sigf(Ai.w); f_ = sigf(Af.w); g_ = tanh_ex(Ag.w); o_ = sigf(Ao.w);
            c_ = fmaf(f_, C1.w, i_ * g_); C1.w = c_; H1r.w = o_ * tanh_ex(c_);
        }
        *reinterpret_cast<float4*>(&sh[OFF_H1 + (1 - p) * (NB * H) + e * H + j0]) = H1r;

        p ^= 1;
    }

    // ================= Final FC: out[b] = dot(Wfc, h1_last) + bfc =================
    float partial = Wf4.x * H1r.x + Wf4.y * H1r.y + Wf4.z * H1r.z + Wf4.w * H1r.w;
    partial += __shfl_xor_sync(0xffffffffu, partial, 8);
    partial += __shfl_xor_sync(0xffffffffu, partial, 4);
    partial += __shfl_xor_sync(0xffffffffu, partial, 2);
    partial += __shfl_xor_sync(0xffffffffu, partial, 1);
    if (hl == 0) {
        out[blockIdx.x * NB + e] = partial + bfc[0];
    }
}

extern "C" void kernel_launch(void* const* d_in, const int* in_sizes, int n_in,
                              void* d_out, int out_size)
{
    const float* x    = (const float*)d_in[0];
    const float* Wih0 = (const float*)d_in[1];
    const float* Whh0 = (const float*)d_in[2];
    const float* bih0 = (const float*)d_in[3];
    const float* bhh0 = (const float*)d_in[4];
    const float* Wih1 = (const float*)d_in[5];
    const float* Whh1 = (const float*)d_in[6];
    const float* bih1 = (const float*)d_in[7];
    const float* bhh1 = (const float*)d_in[8];
    const float* Wfc  = (const float*)d_in[9];
    const float* bfc  = (const float*)d_in[10];
    float* out = (float*)d_out;

    cudaFuncSetAttribute(lstm2_kernel,
                         cudaFuncAttributeMaxDynamicSharedMemorySize, SMEM_BYTES);
    lstm2_kernel<<<NCTAS, NTHREADS, SMEM_BYTES>>>(
        x, Wih0, Whh0, bih0, bhh0, Wih1, Whh1, bih1, bhh1, Wfc, bfc, out);
}

// round 5
// speedup vs baseline: 1.6823x; 1.6823x over previous
#include <cuda_runtime.h>
#include <cstddef>

// Shapes (fixed)
#define T_STEPS 336
#define IN      16
#define H       64
#define NB      8            // batch elements per CTA
#define NT      256          // 8 warps
#define RS      260          // floats per k-row of gate-interleaved weights (64 float4 + pad)

// ---- shared memory layout (float offsets) ----
// Gate-interleaved weights: row k holds 64 float4; float4 j = (Wi[j,k],Wf[j,k],Wg[j,k],Wo[j,k])
#define OFF_WIH0 0
#define OFF_WHH0 (OFF_WIH0 + IN*RS)
#define OFF_WIH1 (OFF_WHH0 + H*RS)
#define OFF_WHH1 (OFF_WIH1 + H*RS)
#define OFF_B0   (OFF_WHH1 + H*RS)   // 64 float4 (bias, gate-interleaved)
#define OFF_B1   (OFF_B0 + 256)
#define OFF_WFC  (OFF_B1 + 256)      // 64
#define OFF_X    (OFF_WFC + 64)      // 8 elems * 16
#define OFF_H0   (OFF_X + 128)       // double buffer 2*8*64
#define OFF_H1   (OFF_H0 + 1024)
#define SMEM_FLOATS (OFF_H1 + 1024)  // 56,832 floats
#define SMEM_BYTES  (SMEM_FLOATS * 4) // 227,328 B

__device__ __forceinline__ float sigf(float x) {
    return 1.0f / (1.0f + __expf(-x));
}
__device__ __forceinline__ float tanh_ex(float x) {
    return 1.0f - 2.0f / (__expf(2.0f * x) + 1.0f);
}
__device__ __forceinline__ float4 ld4(const float* p) {
    return *reinterpret_cast<const float4*>(p);
}
__device__ __forceinline__ void fma4(float4& a, const float4 w, const float s) {
    a.x = fmaf(w.x, s, a.x);
    a.y = fmaf(w.y, s, a.y);
    a.z = fmaf(w.z, s, a.z);
    a.w = fmaf(w.w, s, a.w);
}

// One GEMM segment: NK4 chunks of 4 k's; weights gate-interleaved at wk (advance RS/k);
// inputs for 4 batch elements at hb with element stride EST.
template<int NK4, int EST>
__device__ __forceinline__ void seg(float4 acc[4], const float* __restrict__ wk,
                                    const float* __restrict__ hb)
{
#pragma unroll 4
    for (int c = 0; c < NK4; ++c) {
        const float4 h0 = ld4(hb + 0 * EST + c * 4);
        const float4 h1 = ld4(hb + 1 * EST + c * 4);
        const float4 h2 = ld4(hb + 2 * EST + c * 4);
        const float4 h3 = ld4(hb + 3 * EST + c * 4);
        const float* w = wk + (size_t)c * 4 * RS;
        float4 wv;
        wv = ld4(w);
        fma4(acc[0], wv, h0.x); fma4(acc[1], wv, h1.x); fma4(acc[2], wv, h2.x); fma4(acc[3], wv, h3.x);
        wv = ld4(w + RS);
        fma4(acc[0], wv, h0.y); fma4(acc[1], wv, h1.y); fma4(acc[2], wv, h2.y); fma4(acc[3], wv, h3.y);
        wv = ld4(w + 2 * RS);
        fma4(acc[0], wv, h0.z); fma4(acc[1], wv, h1.z); fma4(acc[2], wv, h2.z); fma4(acc[3], wv, h3.z);
        wv = ld4(w + 3 * RS);
        fma4(acc[0], wv, h0.w); fma4(acc[1], wv, h1.w); fma4(acc[2], wv, h2.w); fma4(acc[3], wv, h3.w);
    }
}

__device__ __forceinline__ void comb(float4& a) {
    a.x += __shfl_xor_sync(0xffffffffu, a.x, 16);
    a.y += __shfl_xor_sync(0xffffffffu, a.y, 16);
    a.z += __shfl_xor_sync(0xffffffffu, a.z, 16);
    a.w += __shfl_xor_sync(0xffffffffu, a.w, 16);
}

// a = (i,f,g,o) pre-activations; updates c, returns h.
__device__ __forceinline__ float actv(const float4 a, float& c) {
    const float i = sigf(a.x);
    const float f = sigf(a.y);
    const float g = tanh_ex(a.z);
    const float o = sigf(a.w);
    c = fmaf(f, c, i * g);
    return o * tanh_ex(c);
}

__global__ void __launch_bounds__(NT, 1)
lstm2_kernel(const float* __restrict__ x,
             const float* __restrict__ Wih0, const float* __restrict__ Whh0,
             const float* __restrict__ bih0, const float* __restrict__ bhh0,
             const float* __restrict__ Wih1, const float* __restrict__ Whh1,
             const float* __restrict__ bih1, const float* __restrict__ bhh1,
             const float* __restrict__ Wfc,  const float* __restrict__ bfc,
             float* __restrict__ out)
{
    extern __shared__ float sh[];
    const int tid = threadIdx.x;

    // ---- Stage weights, gate-interleaved: sh[off + k*RS + j*4 + gate] = W[gate*64+j][k] ----
    for (int idx = tid; idx < 256 * IN; idx += NT) {
        const int gr = idx >> 4, k = idx & 15;          // gr = gate*64 + j
        sh[OFF_WIH0 + k * RS + (gr & 63) * 4 + (gr >> 6)] = Wih0[idx];
    }
    for (int idx = tid; idx < 256 * H; idx += NT) {
        const int gr = idx >> 6, k = idx & 63;
        sh[OFF_WHH0 + k * RS + (gr & 63) * 4 + (gr >> 6)] = Whh0[idx];
    }
    for (int idx = tid; idx < 256 * H; idx += NT) {
        const int gr = idx >> 6, k = idx & 63;
        sh[OFF_WIH1 + k * RS + (gr & 63) * 4 + (gr >> 6)] = Wih1[idx];
    }
    for (int idx = tid; idx < 256 * H; idx += NT) {
        const int gr = idx >> 6, k = idx & 63;
        sh[OFF_WHH1 + k * RS + (gr & 63) * 4 + (gr >> 6)] = Whh1[idx];
    }
    // Biases (combined, gate-interleaved)
    {
        const int idx = tid;  // NT == 256 covers all
        const int gate = idx >> 6, jj = idx & 63;
        sh[OFF_B0 + jj * 4 + gate] = bih0[idx] + bhh0[idx];
        sh[OFF_B1 + jj * 4 + gate] = bih1[idx] + bhh1[idx];
    }
    if (tid < 64) sh[OFF_WFC + tid] = Wfc[tid];
    for (int idx = tid; idx < 1024; idx += NT) {
        sh[OFF_H0 + idx] = 0.0f;
        sh[OFF_H1 + idx] = 0.0f;
    }

    // ---- Thread mapping ----
    // warp 0-3 -> elements 0..3, warp 4-7 -> elements 4..7
    // within element-group: j = (warp&3)*16 + (lane&15); kpar = lane>>4 (split-K half)
    const int warp = tid >> 5, lane = tid & 31;
    const int e0   = (warp >> 2) * 4;
    const int j    = (warp & 3) * 16 + (lane & 15);
    const int jo   = j * 4;
    const int kpar = lane >> 4;

    // x prefetch mapping (first 128 threads)
    const int xe = tid >> 4, xk = tid & 15;
    const float* xptr = x + ((size_t)(blockIdx.x * NB + xe) * T_STEPS) * IN + xk;
    float xreg = (tid < 128) ? xptr[0] : 0.0f;

    __syncthreads();

    const float4 B40 = ld4(&sh[OFF_B0 + jo]);
    const float4 B41 = ld4(&sh[OFF_B1 + jo]);
    const float4 Z4  = make_float4(0.f, 0.f, 0.f, 0.f);
    float c0[4] = {0.f, 0.f, 0.f, 0.f};
    float c1[4] = {0.f, 0.f, 0.f, 0.f};

    int p = 0;
    for (int t = 0; t < T_STEPS; ++t) {
        if (tid < 128) sh[OFF_X + xe * 16 + xk] = xreg;
        __syncthreads();
        if (t + 1 < T_STEPS && tid < 128) xreg = xptr[(size_t)(t + 1) * IN];

        // ================= Layer 0 =================
        float4 acc[4];
        acc[0] = kpar ? Z4 : B40;
        acc[1] = acc[0]; acc[2] = acc[0]; acc[3] = acc[0];

        seg<2, 16>(acc, &sh[OFF_WIH0 + (kpar * 8) * RS + jo],
                        &sh[OFF_X + e0 * 16 + kpar * 8]);
        seg<8, 64>(acc, &sh[OFF_WHH0 + (kpar * 32) * RS + jo],
                        &sh[OFF_H0 + p * 512 + e0 * 64 + kpar * 32]);

        comb(acc[0]); comb(acc[1]); comb(acc[2]); comb(acc[3]);

        float hn0 = actv(acc[0], c0[0]);
        float hn1 = actv(acc[1], c0[1]);
        float hn2 = actv(acc[2], c0[2]);
        float hn3 = actv(acc[3], c0[3]);
        if (!kpar) {
            float* hw = &sh[OFF_H0 + (1 - p) * 512 + e0 * 64 + j];
            hw[0]   = hn0;
            hw[64]  = hn1;
            hw[128] = hn2;
            hw[192] = hn3;
        }
        __syncthreads();

        // ================= Layer 1 =================
        acc[0] = kpar ? Z4 : B41;
        acc[1] = acc[0]; acc[2] = acc[0]; acc[3] = acc[0];

        seg<8, 64>(acc, &sh[OFF_WIH1 + (kpar * 32) * RS + jo],
                        &sh[OFF_H0 + (1 - p) * 512 + e0 * 64 + kpar * 32]);
        seg<8, 64>(acc, &sh[OFF_WHH1 + (kpar * 32) * RS + jo],
                        &sh[OFF_H1 + p * 512 + e0 * 64 + kpar * 32]);

        comb(acc[0]); comb(acc[1]); comb(acc[2]); comb(acc[3]);

        hn0 = actv(acc[0], c1[0]);
        hn1 = actv(acc[1], c1[1]);
        hn2 = actv(acc[2], c1[2]);
        hn3 = actv(acc[3], c1[3]);
        if (!kpar) {
            float* hw = &sh[OFF_H1 + (1 - p) * 512 + e0 * 64 + j];
            hw[0]   = hn0;
            hw[64]  = hn1;
            hw[128] = hn2;
            hw[192] = hn3;
        }
        p ^= 1;
    }

    __syncthreads();

    // ---- FC head: out[b] = dot(Wfc, h1_last[b]) + bfc ----
    if (tid < NB) {
        const float* hv = &sh[OFF_H1 + p * 512 + tid * 64];
        float s = 0.0f;
        #pragma unroll 8
        for (int k = 0; k < H; ++k) s += sh[OFF_WFC + k] * hv[k];
        out[blockIdx.x * NB + tid] = s + bfc[0];
    }
}

extern "C" void kernel_launch(void* const* d_in, const int* in_sizes, int n_in,
                              void* d_out, int out_size)
{
    const float* x    = (const float*)d_in[0];
    const float* Wih0 = (const float*)d_in[1];
    const float* Whh0 = (const float*)d_in[2];
    const float* bih0 = (const float*)d_in[3];
    const float* bhh0 = (const float*)d_in[4];
    const float* Wih1 = (const float*)d_in[5];
    const float* Whh1 = (const float*)d_in[6];
    const float* bih1 = (const float*)d_in[7];
    const float* bhh1 = (const float*)d_in[8];
    const float* Wfc  = (const float*)d_in[9];
    const float* bfc  = (const float*)d_in[10];
    float* out = (float*)d_out;

    cudaFuncSetAttribute(lstm2_kernel,
                         cudaFuncAttributeMaxDynamicSharedMemorySize, SMEM_BYTES);
    lstm2_kernel<<<1024 / NB, NT, SMEM_BYTES>>>(
        x, Wih0, Whh0, bih0, bhh0, Wih1, Whh1, bih1, bhh1, Wfc, bfc, out);
}